// round 8
// baseline (speedup 1.0000x reference)
#include <cuda_runtime.h>
#include <stdint.h>

// Sparse Adagrad on GB300 (sm_103a) — gather formulation, self-cleaning buckets.
//
//   m_new[v] = m[v] + sum_i g_i^2
//   w_new[v] = w[v] - lr * (sum_i g_i) / (sqrt(m_new[v]) + eps)
//
// Inverse index map as per-bucket linked lists: g_head[v] holds (row+1) or 0
// (empty). 0-encoding matches static zero-init of __device__ globals, and the
// fused kernel resets each consumed head to 0, so every graph replay starts
// from a clean all-zero head array — no init kernel needed.
//
// Output layout: out[0:V*D] = weights_new, out[V*D:2*V*D] = moments_new.
// indices arrive as int32 (JAX x64 disabled). valid_count=200000 static.

#define EPS 1e-10f
#define D 64
#define CHUNKS 16            // D/4 float4 chunks per row
#define VALID_COUNT 200000
#define V_MAX 500000
#define N_MAX 262144

__device__ int g_head[V_MAX];   // 0 = empty, else gradient_row+1 (zero-init)
__device__ int g_next[N_MAX];   // same encoding: old head value

__global__ void build_lists_kernel(const int* __restrict__ idx)
{
    int i = blockIdx.x * blockDim.x + threadIdx.x;
    if (i >= VALID_COUNT) return;
    int v = idx[i];
    g_next[i] = atomicExch(&g_head[v], i + 1);
}

__global__ void fused_adagrad_kernel(const float4* __restrict__ g,   // [N, 16]
                                     const float4* __restrict__ w,   // [V, 16]
                                     const float4* __restrict__ m,   // [V, 16]
                                     const float* __restrict__ lr_ptr,
                                     float4* __restrict__ out_w,     // [V, 16]
                                     float4* __restrict__ out_m,     // [V, 16]
                                     int V)
{
    long t = (long)blockIdx.x * blockDim.x + threadIdx.x;
    long total = (long)V * CHUNKS;
    if (t >= total) return;
    int v = (int)(t >> 4);        // output row
    int chunk = (int)(t & 15);
    long off = (long)v * CHUNKS + chunk;

    float lr = __ldg(lr_ptr);
    // Touch-once streaming loads: evict-first so the 256 MB w/m stream does
    // not thrash L2 (keep L2 for gradient rows + bucket metadata).
    float4 mv = __ldcs(&m[off]);
    float4 wv = __ldcs(&w[off]);

    int e = g_head[v];            // all 16 lanes of row v are in one warp
    if (e > 0) {
        if (chunk == 0)
            g_head[v] = 0;        // self-clean for the next graph replay
                                  // (safe: lane loads above precede this store
                                  //  in SIMT program order within the warp)
        float4 sg  = make_float4(0.f, 0.f, 0.f, 0.f);
        float4 sg2 = make_float4(0.f, 0.f, 0.f, 0.f);
        do {
            int i = e - 1;
            float4 gv = g[(long)i * CHUNKS + chunk];
            sg.x += gv.x;  sg.y += gv.y;  sg.z += gv.z;  sg.w += gv.w;
            sg2.x = fmaf(gv.x, gv.x, sg2.x);
            sg2.y = fmaf(gv.y, gv.y, sg2.y);
            sg2.z = fmaf(gv.z, gv.z, sg2.z);
            sg2.w = fmaf(gv.w, gv.w, sg2.w);
            e = g_next[i];
        } while (e > 0);

        mv.x += sg2.x;  mv.y += sg2.y;  mv.z += sg2.z;  mv.w += sg2.w;

        wv.x -= lr * sg.x / (sqrtf(mv.x) + EPS);
        wv.y -= lr * sg.y / (sqrtf(mv.y) + EPS);
        wv.z -= lr * sg.z / (sqrtf(mv.z) + EPS);
        wv.w -= lr * sg.w / (sqrtf(mv.w) + EPS);
    }

    // Touch-once streaming stores.
    __stcs(&out_w[off], wv);
    __stcs(&out_m[off], mv);
}

extern "C" void kernel_launch(void* const* d_in, const int* in_sizes, int n_in,
                              void* d_out, int out_size)
{
    const float* gradients = (const float*)d_in[0];   // [N, 64]
    const float* weights   = (const float*)d_in[1];   // [V, 64]
    const float* moments   = (const float*)d_in[2];   // [V, 64]
    const int*   indices   = (const int*)d_in[3];     // [N] int32
    const float* lr        = (const float*)d_in[4];   // scalar

    long VD = (long)in_sizes[1];          // V*D = 32,000,000
    int  V  = (int)(VD / D);              // 500,000
    float* out_w = (float*)d_out;
    float* out_m = (float*)d_out + VD;

    // 1. build per-bucket linked lists (heads are all-zero: static init on
    //    first run, self-cleaned by the fused kernel on every run)
    build_lists_kernel<<<(VALID_COUNT + 255) / 256, 256>>>(indices);

    // 2. fused gather + update + write (single full pass over output)
    {
        long total = (long)V * CHUNKS;    // 8M threads
        int threads = 256;
        int blocks = (int)((total + threads - 1) / threads);
        fused_adagrad_kernel<<<blocks, threads>>>((const float4*)gradients,
                                                  (const float4*)weights,
                                                  (const float4*)moments,
                                                  lr,
                                                  (float4*)out_w,
                                                  (float4*)out_m,
                                                  V);
    }
}